// round 12
// baseline (speedup 1.0000x reference)
#include <cuda_runtime.h>
#include <cuda_bf16.h>
#include <cstdint>
#include <math.h>

#define T_SEQ  128
#define BATCH  32
#define HID    1024
#define VOCAB  32000
#define MROWS  (T_SEQ * BATCH)      // 4096
#define RNN_CTAS 64
#define RNN_COLS 16                 // HID / RNN_CTAS
#define WH_STRIDE 1028              // 1024 + 4 pad (floats)

// ---------------- scratch (device globals; allocation is forbidden) ----------------
__device__ float          g_x0[MROWS * HID];
__device__ float          g_xw[MROWS * HID];
__device__ float          g_y0[MROWS * HID];
__device__ __nv_bfloat16  g_y1b[MROWS * HID];
__device__ __nv_bfloat16  g_woutb[(size_t)VOCAB * HID];
__device__ float          g_hbuf0[BATCH * HID];
__device__ float          g_hbuf1[BATCH * HID];
__device__ float          g_hfin[2 * BATCH * HID];
// one flag per CTA, 128B apart (monotonic step counters; uniform at launch edges)
__device__ __align__(128) unsigned g_flags[RNN_CTAS * 32];

// ---------------- helpers ----------------
__device__ __forceinline__ uint32_t smaddr(const void* p) {
    return (uint32_t)__cvta_generic_to_shared(p);
}
__device__ __forceinline__ void cp16(uint32_t dst, const void* src) {
    asm volatile("cp.async.ca.shared.global [%0], [%1], 16;" :: "r"(dst), "l"(src));
}
__device__ __forceinline__ void cp_commit() { asm volatile("cp.async.commit_group;"); }
template <int N> __device__ __forceinline__ void cp_wait() {
    asm volatile("cp.async.wait_group %0;" :: "n"(N));
}
__device__ __forceinline__ float f2tf(float x) {
    uint32_t r; asm("cvt.rna.tf32.f32 %0, %1;" : "=r"(r) : "f"(x));
    return __uint_as_float(r);
}
__device__ __forceinline__ uint32_t t32(float x) {
    uint32_t r; asm("cvt.rna.tf32.f32 %0, %1;" : "=r"(r) : "f"(x));
    return r;
}
__device__ __forceinline__ uint32_t fbits(float x) { return __float_as_uint(x); }

__device__ __forceinline__ void mma_tf32(float* c, const uint32_t* a, const uint32_t* b) {
    asm volatile(
        "mma.sync.aligned.m16n8k8.row.col.f32.tf32.tf32.f32 "
        "{%0,%1,%2,%3}, {%4,%5,%6,%7}, {%8,%9}, {%0,%1,%2,%3};"
        : "+f"(c[0]), "+f"(c[1]), "+f"(c[2]), "+f"(c[3])
        : "r"(a[0]), "r"(a[1]), "r"(a[2]), "r"(a[3]), "r"(b[0]), "r"(b[1]));
}
__device__ __forceinline__ void mma_bf16(float* c, const uint32_t* a, const uint32_t* b) {
    asm volatile(
        "mma.sync.aligned.m16n8k16.row.col.f32.bf16.bf16.f32 "
        "{%0,%1,%2,%3}, {%4,%5,%6,%7}, {%8,%9}, {%0,%1,%2,%3};"
        : "+f"(c[0]), "+f"(c[1]), "+f"(c[2]), "+f"(c[3])
        : "r"(a[0]), "r"(a[1]), "r"(a[2]), "r"(a[3]), "r"(b[0]), "r"(b[1]));
}

// ---------------- embedding gather ----------------
__global__ void __launch_bounds__(256) embed_kernel(const int* __restrict__ tok,
                                                    const float* __restrict__ emb) {
    int row = blockIdx.x;
    int t = tok[row];
    const float4* s = (const float4*)(emb + (size_t)t * HID);
    float4* d = (float4*)(g_x0 + (size_t)row * HID);
    d[threadIdx.x] = s[threadIdx.x];
}

// ---------------- W_out f32 -> bf16 ----------------
__global__ void __launch_bounds__(256) cvt_wout_kernel(const float* __restrict__ w) {
    size_t i = ((size_t)blockIdx.x * 256 + threadIdx.x) * 4;
    float4 v = *(const float4*)(w + i);
    __nv_bfloat162 p0, p1;
    p0.x = __float2bfloat16_rn(v.x); p0.y = __float2bfloat16_rn(v.y);
    p1.x = __float2bfloat16_rn(v.z); p1.y = __float2bfloat16_rn(v.w);
    *(__nv_bfloat162*)(g_woutb + i)     = p0;
    *(__nv_bfloat162*)(g_woutb + i + 2) = p1;
}

// ---------------- tf32 GEMM: C[M,N] = A[M,K] @ B[N,K]^T + biasA[n] + biasB[n] ----------------
__global__ void __launch_bounds__(256) gemm_tf32_kernel(
    const float* __restrict__ A, const float* __restrict__ B,
    const float* __restrict__ biasA, const float* __restrict__ biasB,
    float* __restrict__ C, int M, int N, int K)
{
    __shared__ __align__(16) float As[128 * 20];
    __shared__ __align__(16) float Bs[128 * 20];
    int tid = threadIdx.x, warp = tid >> 5, lane = tid & 31;
    int bm = blockIdx.y * 128, bn = blockIdx.x * 128;
    int mB = (warp >> 2) * 64, nB = (warp & 3) * 32;
    int r = lane >> 2, cc = lane & 3;

    float acc[4][4][4];
#pragma unroll
    for (int i = 0; i < 4; i++)
#pragma unroll
        for (int j = 0; j < 4; j++)
#pragma unroll
            for (int q = 0; q < 4; q++) acc[i][j][q] = 0.f;

    for (int k0 = 0; k0 < K; k0 += 16) {
        __syncthreads();
#pragma unroll
        for (int i = 0; i < 2; i++) {
            int q = i * 256 + tid;
            int rr = q >> 2, c4 = (q & 3) * 4;
            float4 va = *(const float4*)(A + (size_t)(bm + rr) * K + k0 + c4);
            float4 ta = make_float4(f2tf(va.x), f2tf(va.y), f2tf(va.z), f2tf(va.w));
            *(float4*)&As[rr * 20 + c4] = ta;
            float4 vb = *(const float4*)(B + (size_t)(bn + rr) * K + k0 + c4);
            float4 tb = make_float4(f2tf(vb.x), f2tf(vb.y), f2tf(vb.z), f2tf(vb.w));
            *(float4*)&Bs[rr * 20 + c4] = tb;
        }
        __syncthreads();
#pragma unroll
        for (int ks = 0; ks < 2; ks++) {
            int k = ks * 8;
            uint32_t af[4][4], bf[4][2];
#pragma unroll
            for (int mt = 0; mt < 4; mt++) {
                const float* ap = &As[(mB + mt * 16 + r) * 20 + k + cc];
                af[mt][0] = fbits(ap[0]);
                af[mt][1] = fbits(ap[8 * 20]);
                af[mt][2] = fbits(ap[4]);
                af[mt][3] = fbits(ap[8 * 20 + 4]);
            }
#pragma unroll
            for (int nt = 0; nt < 4; nt++) {
                const float* bp = &Bs[(nB + nt * 8 + r) * 20 + k + cc];
                bf[nt][0] = fbits(bp[0]);
                bf[nt][1] = fbits(bp[4]);
            }
#pragma unroll
            for (int mt = 0; mt < 4; mt++)
#pragma unroll
                for (int nt = 0; nt < 4; nt++)
                    mma_tf32(acc[mt][nt], af[mt], bf[nt]);
        }
    }
#pragma unroll
    for (int mt = 0; mt < 4; mt++)
#pragma unroll
        for (int nt = 0; nt < 4; nt++) {
            int row = bm + mB + mt * 16 + r;
            int col = bn + nB + nt * 8 + cc * 2;
            float b0 = biasA[col] + biasB[col];
            float b1 = biasA[col + 1] + biasB[col + 1];
            float2 v0 = make_float2(acc[mt][nt][0] + b0, acc[mt][nt][1] + b1);
            float2 v1 = make_float2(acc[mt][nt][2] + b0, acc[mt][nt][3] + b1);
            *(float2*)(C + (size_t)row * N + col)       = v0;
            *(float2*)(C + (size_t)(row + 8) * N + col) = v1;
        }
}

// ---------------- bf16 GEMM: C[M,N] = A[M,K] @ B[N,K]^T + bias[n] ----------------
__global__ void __launch_bounds__(256) gemm_bf16_kernel(
    const __nv_bfloat16* __restrict__ A, const __nv_bfloat16* __restrict__ B,
    const float* __restrict__ bias, float* __restrict__ C, int M, int N, int K)
{
    __shared__ __align__(16) __nv_bfloat16 As[2][128 * 40];
    __shared__ __align__(16) __nv_bfloat16 Bs[2][128 * 40];
    int tid = threadIdx.x, warp = tid >> 5, lane = tid & 31;
    int bm = blockIdx.y * 128, bn = blockIdx.x * 128;
    int mB = (warp >> 2) * 64, nB = (warp & 3) * 32;
    int r = lane >> 2, cc = lane & 3;

    float acc[4][4][4];
#pragma unroll
    for (int i = 0; i < 4; i++)
#pragma unroll
        for (int j = 0; j < 4; j++)
#pragma unroll
            for (int q = 0; q < 4; q++) acc[i][j][q] = 0.f;

    int rr0 = tid >> 2, c8 = (tid & 3) * 8;
    const int KT = K / 32;

    {
        cp16(smaddr(&As[0][rr0 * 40 + c8]), A + (size_t)(bm + rr0) * K + c8);
        cp16(smaddr(&Bs[0][rr0 * 40 + c8]), B + (size_t)(bn + rr0) * K + c8);
        int rr1 = rr0 + 64;
        cp16(smaddr(&As[0][rr1 * 40 + c8]), A + (size_t)(bm + rr1) * K + c8);
        cp16(smaddr(&Bs[0][rr1 * 40 + c8]), B + (size_t)(bn + rr1) * K + c8);
        cp_commit();
    }

    for (int kt = 0; kt < KT; kt++) {
        int st = kt & 1;
        if (kt + 1 < KT) {
            int k0 = (kt + 1) * 32;
            cp16(smaddr(&As[st ^ 1][rr0 * 40 + c8]), A + (size_t)(bm + rr0) * K + k0 + c8);
            cp16(smaddr(&Bs[st ^ 1][rr0 * 40 + c8]), B + (size_t)(bn + rr0) * K + k0 + c8);
            int rr1 = rr0 + 64;
            cp16(smaddr(&As[st ^ 1][rr1 * 40 + c8]), A + (size_t)(bm + rr1) * K + k0 + c8);
            cp16(smaddr(&Bs[st ^ 1][rr1 * 40 + c8]), B + (size_t)(bn + rr1) * K + k0 + c8);
            cp_commit();
            cp_wait<1>();
        } else {
            cp_wait<0>();
        }
        __syncthreads();
#pragma unroll
        for (int ks = 0; ks < 2; ks++) {
            int k = ks * 16;
            uint32_t af[4][4], bf[4][2];
#pragma unroll
            for (int mt = 0; mt < 4; mt++) {
                const __nv_bfloat16* ap = &As[st][(mB + mt * 16 + r) * 40 + k + cc * 2];
                af[mt][0] = *(const uint32_t*)(ap);
                af[mt][1] = *(const uint32_t*)(ap + 8 * 40);
                af[mt][2] = *(const uint32_t*)(ap + 8);
                af[mt][3] = *(const uint32_t*)(ap + 8 * 40 + 8);
            }
#pragma unroll
            for (int nt = 0; nt < 4; nt++) {
                const __nv_bfloat16* bp = &Bs[st][(nB + nt * 8 + r) * 40 + k + cc * 2];
                bf[nt][0] = *(const uint32_t*)(bp);
                bf[nt][1] = *(const uint32_t*)(bp + 8);
            }
#pragma unroll
            for (int mt = 0; mt < 4; mt++)
#pragma unroll
                for (int nt = 0; nt < 4; nt++)
                    mma_bf16(acc[mt][nt], af[mt], bf[nt]);
        }
        __syncthreads();
    }
#pragma unroll
    for (int mt = 0; mt < 4; mt++)
#pragma unroll
        for (int nt = 0; nt < 4; nt++) {
            int row = bm + mB + mt * 16 + r;
            int col = bn + nB + nt * 8 + cc * 2;
            float b0 = bias[col], b1 = bias[col + 1];
            float2 v0 = make_float2(acc[mt][nt][0] + b0, acc[mt][nt][1] + b1);
            float2 v1 = make_float2(acc[mt][nt][2] + b0, acc[mt][nt][3] + b1);
            *(float2*)(C + (size_t)row * N + col)       = v0;
            *(float2*)(C + (size_t)(row + 8) * N + col) = v1;
        }
}

// ---------------- persistent RNN layer: flag barrier + direct-L2 fragment loads ----------------
__global__ void __launch_bounds__(256) rnn_layer_kernel(
    const float* __restrict__ xW, const float* __restrict__ Wh,
    const float* __restrict__ h0,
    float* __restrict__ yf, __nv_bfloat16* __restrict__ yb,
    float* __restrict__ hfin, int writeBf)
{
    extern __shared__ float dyn[];
    float* Whs = dyn;                            // [16][WH_STRIDE] tf32
    float* red = Whs + RNN_COLS * WH_STRIDE;     // [8][512]

    int tid = threadIdx.x, warp = tid >> 5, lane = tid & 31;
    int r = lane >> 2, cc = lane & 3;
    int colBase = blockIdx.x * RNN_COLS;
    int kw = warp * 128;

    // uniform-at-launch base of the flag counters (only this CTA writes its flag)
    unsigned base = *(volatile unsigned*)&g_flags[blockIdx.x * 32];

    // weight slice, tf32-rounded, once
    for (int i4 = tid; i4 < RNN_COLS * 256; i4 += 256) {
        int n = i4 >> 8, c4 = (i4 & 255) * 4;
        float4 v = *(const float4*)(Wh + (size_t)(colBase + n) * HID + c4);
        *(float4*)&Whs[n * WH_STRIDE + c4] =
            make_float4(f2tf(v.x), f2tf(v.y), f2tf(v.z), f2tf(v.w));
    }
    __syncthreads();

    int ob = tid >> 3;
    int on = (tid * 2) & 15;
    const float* xwp = xW + (size_t)ob * HID + colBase + on;
    float2 xwv = *(const float2*)xwp;

    for (int t = 0; t < T_SEQ; t++) {
        const float* hprev = (t == 0) ? h0 : ((t & 1) ? g_hbuf0 : g_hbuf1);
        float* hnext = (t & 1) ? g_hbuf1 : g_hbuf0;

        // warp-local partial GEMM; A-fragments streamed straight from L2
        float acc[2][2][4];
#pragma unroll
        for (int mt = 0; mt < 2; mt++)
#pragma unroll
            for (int nt = 0; nt < 2; nt++)
#pragma unroll
                for (int q = 0; q < 4; q++) acc[mt][nt][q] = 0.f;

#pragma unroll
        for (int kt = 0; kt < 16; kt++) {
            int k0 = kw + kt * 8;
            uint32_t af[2][4], bf[2][2];
#pragma unroll
            for (int mt = 0; mt < 2; mt++) {
                const float* ag = hprev + (size_t)(mt * 16 + r) * HID + k0 + cc;
                af[mt][0] = t32(__ldcg(ag));
                af[mt][1] = t32(__ldcg(ag + 8 * HID));
                af[mt][2] = t32(__ldcg(ag + 4));
                af[mt][3] = t32(__ldcg(ag + 8 * HID + 4));
            }
#pragma unroll
            for (int nt = 0; nt < 2; nt++) {
                const float* bp = &Whs[(nt * 8 + r) * WH_STRIDE + k0 + cc];
                bf[nt][0] = fbits(bp[0]);
                bf[nt][1] = fbits(bp[4]);
            }
#pragma unroll
            for (int mt = 0; mt < 2; mt++)
#pragma unroll
                for (int nt = 0; nt < 2; nt++)
                    mma_tf32(acc[mt][nt], af[mt], bf[nt]);
        }

#pragma unroll
        for (int mt = 0; mt < 2; mt++)
#pragma unroll
            for (int nt = 0; nt < 2; nt++) {
                int b = mt * 16 + r, n = nt * 8 + 2 * cc;
                *(float2*)&red[warp * 512 + b * 16 + n] =
                    make_float2(acc[mt][nt][0], acc[mt][nt][1]);
                *(float2*)&red[warp * 512 + (b + 8) * 16 + n] =
                    make_float2(acc[mt][nt][2], acc[mt][nt][3]);
            }
        __syncthreads();

        int o = tid * 2;
        float sx = 0.f, sy = 0.f;
#pragma unroll
        for (int w = 0; w < 8; w++) {
            float2 v = *(float2*)&red[w * 512 + o];
            sx += v.x; sy += v.y;
        }
        float v0 = tanhf(sx + xwv.x);
        float v1 = tanhf(sy + xwv.y);
        __stcg((float2*)(hnext + ob * HID + colBase + on), make_float2(v0, v1));
        __syncthreads();   // all h stores done (cumulativity for the release below)

        // arrive: publish this CTA's step (release orders the h stores)
        if (t + 1 < T_SEQ && tid == 0)
            asm volatile("st.release.gpu.u32 [%0], %1;"
                         :: "l"(&g_flags[blockIdx.x * 32]), "r"(base + t + 1) : "memory");

        // overlapped with flag propagation: outputs + next xW prefetch
        if (t + 1 < T_SEQ)
            xwv = *(const float2*)(xwp + (size_t)(t + 1) * BATCH * HID);
        size_t oofs = (size_t)(t * BATCH + ob) * HID + colBase + on;
        *(float2*)(yf + oofs) = make_float2(v0, v1);
        if (writeBf) {
            __nv_bfloat162 pb;
            pb.x = __float2bfloat16_rn(v0);
            pb.y = __float2bfloat16_rn(v1);
            *(__nv_bfloat162*)(yb + oofs) = pb;
        }
        if (t == T_SEQ - 1)
            *(float2*)(hfin + ob * HID + colBase + on) = make_float2(v0, v1);

        // wait: threads 0..63 each watch one CTA's flag
        if (t + 1 < T_SEQ) {
            if (tid < RNN_CTAS) {
                unsigned tgt = base + t + 1, g;
                do {
                    asm volatile("ld.acquire.gpu.u32 %0, [%1];"
                                 : "=r"(g) : "l"(&g_flags[tid * 32]) : "memory");
                } while ((int)(g - tgt) < 0);
            }
            __syncthreads();
        }
    }
}

// ---------------- log_softmax over rows of 32000 ----------------
__device__ __forceinline__ void comb(float& m, float& s, float m2, float s2) {
    float nm = fmaxf(m, m2);
    s = s * __expf(m - nm) + s2 * __expf(m2 - nm);
    m = nm;
}
__global__ void __launch_bounds__(256) logsoftmax_kernel(float* __restrict__ out) {
    __shared__ float sm[8], ss[8], bm, bs;
    float* row = out + (size_t)blockIdx.x * VOCAB;
    int tid = threadIdx.x;
    float m = -1e30f, s = 0.f;
    for (int i = tid; i < VOCAB / 4; i += 256) {
        float4 v = *(const float4*)(row + i * 4);
        comb(m, s, v.x, 1.f); comb(m, s, v.y, 1.f);
        comb(m, s, v.z, 1.f); comb(m, s, v.w, 1.f);
    }
#pragma unroll
    for (int o = 16; o > 0; o >>= 1) {
        float m2 = __shfl_xor_sync(0xffffffffu, m, o);
        float s2 = __shfl_xor_sync(0xffffffffu, s, o);
        comb(m, s, m2, s2);
    }
    if ((tid & 31) == 0) { sm[tid >> 5] = m; ss[tid >> 5] = s; }
    __syncthreads();
    if (tid == 0) {
        float M = sm[0], S = ss[0];
#pragma unroll
        for (int w = 1; w < 8; w++) comb(M, S, sm[w], ss[w]);
        bm = M; bs = logf(S);
    }
    __syncthreads();
    float sub = bm + bs;
    for (int i = tid; i < VOCAB / 4; i += 256) {
        float4 v = *(const float4*)(row + i * 4);
        v.x -= sub; v.y -= sub; v.z -= sub; v.w -= sub;
        *(float4*)(row + i * 4) = v;
    }
}

// ---------------- append final hidden states ----------------
__global__ void __launch_bounds__(256) copy_hidden_kernel(float* __restrict__ dst) {
    int i = blockIdx.x * 256 + threadIdx.x;
    dst[i] = g_hfin[i];
}

// ---------------- launch ----------------
extern "C" void kernel_launch(void* const* d_in, const int* in_sizes, int n_in,
                              void* d_out, int out_size) {
    const int*   tok    = (const int*)d_in[0];
    const float* hidden = (const float*)d_in[1];
    const float* emb    = (const float*)d_in[2];
    const float* W_ih   = (const float*)d_in[3];
    const float* W_hh   = (const float*)d_in[4];
    const float* b_ih   = (const float*)d_in[5];
    const float* b_hh   = (const float*)d_in[6];
    const float* W_out  = (const float*)d_in[7];
    const float* b_out  = (const float*)d_in[8];
    float* out = (float*)d_out;

    void *p_x0, *p_xw, *p_y0, *p_y1b, *p_hfin, *p_wb;
    cudaGetSymbolAddress(&p_x0, g_x0);
    cudaGetSymbolAddress(&p_xw, g_xw);
    cudaGetSymbolAddress(&p_y0, g_y0);
    cudaGetSymbolAddress(&p_y1b, g_y1b);
    cudaGetSymbolAddress(&p_hfin, g_hfin);
    cudaGetSymbolAddress(&p_wb, g_woutb);

    const int rnn_smem = RNN_COLS * WH_STRIDE * 4 + 8 * 512 * 4;
    cudaFuncSetAttribute(rnn_layer_kernel,
                         cudaFuncAttributeMaxDynamicSharedMemorySize, rnn_smem);

    embed_kernel<<<MROWS, 256>>>(tok, emb);
    cvt_wout_kernel<<<VOCAB, 256>>>(W_out);

    // layer 0
    gemm_tf32_kernel<<<dim3(HID / 128, MROWS / 128), 256>>>(
        (const float*)p_x0, W_ih, b_ih, b_hh, (float*)p_xw, MROWS, HID, HID);
    rnn_layer_kernel<<<RNN_CTAS, 256, rnn_smem>>>(
        (const float*)p_xw, W_hh, hidden,
        (float*)p_y0, (__nv_bfloat16*)p_y1b, (float*)p_hfin, 0);

    // layer 1
    gemm_tf32_kernel<<<dim3(HID / 128, MROWS / 128), 256>>>(
        (const float*)p_y0, W_ih + (size_t)HID * HID, b_ih + HID, b_hh + HID,
        (float*)p_xw, MROWS, HID, HID);
    rnn_layer_kernel<<<RNN_CTAS, 256, rnn_smem>>>(
        (const float*)p_xw, W_hh + (size_t)HID * HID, hidden + BATCH * HID,
        (float*)p_y0, (__nv_bfloat16*)p_y1b, (float*)p_hfin + BATCH * HID, 1);

    // output projection + log_softmax
    gemm_bf16_kernel<<<dim3(VOCAB / 128, MROWS / 128), 256>>>(
        (const __nv_bfloat16*)p_y1b, (const __nv_bfloat16*)p_wb, b_out, out,
        MROWS, VOCAB, HID);
    logsoftmax_kernel<<<MROWS, 256>>>(out);

    size_t logits_elems = (size_t)MROWS * VOCAB;
    if ((size_t)out_size >= logits_elems + 2 * BATCH * HID)
        copy_hidden_kernel<<<(2 * BATCH * HID) / 256, 256>>>(out + logits_elems);
}

// round 13
// speedup vs baseline: 1.8333x; 1.8333x over previous
#include <cuda_runtime.h>
#include <cuda_bf16.h>
#include <cstdint>
#include <math.h>

#define T_SEQ  128
#define BATCH  32
#define HID    1024
#define VOCAB  32000
#define MROWS  (T_SEQ * BATCH)      // 4096
#define RNN_CTAS 64
#define RNN_COLS 16                 // HID / RNN_CTAS
#define WH_STRIDE 1028              // 1024 + 4 pad (floats)

// ---------------- scratch (device globals; allocation is forbidden) ----------------
__device__ float          g_x0[MROWS * HID];
__device__ float          g_xw[MROWS * HID];
__device__ float          g_y0[MROWS * HID];
__device__ __nv_bfloat16  g_y1b[MROWS * HID];
__device__ __nv_bfloat16  g_woutb[(size_t)VOCAB * HID];
__device__ float          g_hbuf0[BATCH * HID];
__device__ float          g_hbuf1[BATCH * HID];
__device__ float          g_hfin[2 * BATCH * HID];
// one flag per CTA, 128B apart (monotonic step counters; uniform at launch edges)
__device__ __align__(128) unsigned g_flags[RNN_CTAS * 32];

// ---------------- helpers ----------------
__device__ __forceinline__ uint32_t smaddr(const void* p) {
    return (uint32_t)__cvta_generic_to_shared(p);
}
__device__ __forceinline__ void cp16(uint32_t dst, const void* src) {
    asm volatile("cp.async.ca.shared.global [%0], [%1], 16;" :: "r"(dst), "l"(src));
}
__device__ __forceinline__ void cp_commit() { asm volatile("cp.async.commit_group;"); }
template <int N> __device__ __forceinline__ void cp_wait() {
    asm volatile("cp.async.wait_group %0;" :: "n"(N));
}
__device__ __forceinline__ float f2tf(float x) {
    uint32_t r; asm("cvt.rna.tf32.f32 %0, %1;" : "=r"(r) : "f"(x));
    return __uint_as_float(r);
}
__device__ __forceinline__ uint32_t t32(float x) {
    uint32_t r; asm("cvt.rna.tf32.f32 %0, %1;" : "=r"(r) : "f"(x));
    return r;
}
__device__ __forceinline__ uint32_t fbits(float x) { return __float_as_uint(x); }

__device__ __forceinline__ void mma_tf32(float* c, const uint32_t* a, const uint32_t* b) {
    asm volatile(
        "mma.sync.aligned.m16n8k8.row.col.f32.tf32.tf32.f32 "
        "{%0,%1,%2,%3}, {%4,%5,%6,%7}, {%8,%9}, {%0,%1,%2,%3};"
        : "+f"(c[0]), "+f"(c[1]), "+f"(c[2]), "+f"(c[3])
        : "r"(a[0]), "r"(a[1]), "r"(a[2]), "r"(a[3]), "r"(b[0]), "r"(b[1]));
}
__device__ __forceinline__ void mma_bf16(float* c, const uint32_t* a, const uint32_t* b) {
    asm volatile(
        "mma.sync.aligned.m16n8k16.row.col.f32.bf16.bf16.f32 "
        "{%0,%1,%2,%3}, {%4,%5,%6,%7}, {%8,%9}, {%0,%1,%2,%3};"
        : "+f"(c[0]), "+f"(c[1]), "+f"(c[2]), "+f"(c[3])
        : "r"(a[0]), "r"(a[1]), "r"(a[2]), "r"(a[3]), "r"(b[0]), "r"(b[1]));
}

// ---------------- embedding gather ----------------
__global__ void __launch_bounds__(256) embed_kernel(const int* __restrict__ tok,
                                                    const float* __restrict__ emb) {
    int row = blockIdx.x;
    int t = tok[row];
    const float4* s = (const float4*)(emb + (size_t)t * HID);
    float4* d = (float4*)(g_x0 + (size_t)row * HID);
    d[threadIdx.x] = s[threadIdx.x];
}

// ---------------- W_out f32 -> bf16 ----------------
__global__ void __launch_bounds__(256) cvt_wout_kernel(const float* __restrict__ w) {
    size_t i = ((size_t)blockIdx.x * 256 + threadIdx.x) * 4;
    float4 v = *(const float4*)(w + i);
    __nv_bfloat162 p0, p1;
    p0.x = __float2bfloat16_rn(v.x); p0.y = __float2bfloat16_rn(v.y);
    p1.x = __float2bfloat16_rn(v.z); p1.y = __float2bfloat16_rn(v.w);
    *(__nv_bfloat162*)(g_woutb + i)     = p0;
    *(__nv_bfloat162*)(g_woutb + i + 2) = p1;
}

// ---------------- tf32 GEMM: C[M,N] = A[M,K] @ B[N,K]^T + biasA[n] + biasB[n] ----------------
__global__ void __launch_bounds__(256) gemm_tf32_kernel(
    const float* __restrict__ A, const float* __restrict__ B,
    const float* __restrict__ biasA, const float* __restrict__ biasB,
    float* __restrict__ C, int M, int N, int K)
{
    __shared__ __align__(16) float As[128 * 20];
    __shared__ __align__(16) float Bs[128 * 20];
    int tid = threadIdx.x, warp = tid >> 5, lane = tid & 31;
    int bm = blockIdx.y * 128, bn = blockIdx.x * 128;
    int mB = (warp >> 2) * 64, nB = (warp & 3) * 32;
    int r = lane >> 2, cc = lane & 3;

    float acc[4][4][4];
#pragma unroll
    for (int i = 0; i < 4; i++)
#pragma unroll
        for (int j = 0; j < 4; j++)
#pragma unroll
            for (int q = 0; q < 4; q++) acc[i][j][q] = 0.f;

    for (int k0 = 0; k0 < K; k0 += 16) {
        __syncthreads();
#pragma unroll
        for (int i = 0; i < 2; i++) {
            int q = i * 256 + tid;
            int rr = q >> 2, c4 = (q & 3) * 4;
            float4 va = *(const float4*)(A + (size_t)(bm + rr) * K + k0 + c4);
            float4 ta = make_float4(f2tf(va.x), f2tf(va.y), f2tf(va.z), f2tf(va.w));
            *(float4*)&As[rr * 20 + c4] = ta;
            float4 vb = *(const float4*)(B + (size_t)(bn + rr) * K + k0 + c4);
            float4 tb = make_float4(f2tf(vb.x), f2tf(vb.y), f2tf(vb.z), f2tf(vb.w));
            *(float4*)&Bs[rr * 20 + c4] = tb;
        }
        __syncthreads();
#pragma unroll
        for (int ks = 0; ks < 2; ks++) {
            int k = ks * 8;
            uint32_t af[4][4], bf[4][2];
#pragma unroll
            for (int mt = 0; mt < 4; mt++) {
                const float* ap = &As[(mB + mt * 16 + r) * 20 + k + cc];
                af[mt][0] = fbits(ap[0]);
                af[mt][1] = fbits(ap[8 * 20]);
                af[mt][2] = fbits(ap[4]);
                af[mt][3] = fbits(ap[8 * 20 + 4]);
            }
#pragma unroll
            for (int nt = 0; nt < 4; nt++) {
                const float* bp = &Bs[(nB + nt * 8 + r) * 20 + k + cc];
                bf[nt][0] = fbits(bp[0]);
                bf[nt][1] = fbits(bp[4]);
            }
#pragma unroll
            for (int mt = 0; mt < 4; mt++)
#pragma unroll
                for (int nt = 0; nt < 4; nt++)
                    mma_tf32(acc[mt][nt], af[mt], bf[nt]);
        }
    }
#pragma unroll
    for (int mt = 0; mt < 4; mt++)
#pragma unroll
        for (int nt = 0; nt < 4; nt++) {
            int row = bm + mB + mt * 16 + r;
            int col = bn + nB + nt * 8 + cc * 2;
            float b0 = biasA[col] + biasB[col];
            float b1 = biasA[col + 1] + biasB[col + 1];
            float2 v0 = make_float2(acc[mt][nt][0] + b0, acc[mt][nt][1] + b1);
            float2 v1 = make_float2(acc[mt][nt][2] + b0, acc[mt][nt][3] + b1);
            *(float2*)(C + (size_t)row * N + col)       = v0;
            *(float2*)(C + (size_t)(row + 8) * N + col) = v1;
        }
}

// ---------------- bf16 GEMM: C[M,N] = A[M,K] @ B[N,K]^T + bias[n] ----------------
__global__ void __launch_bounds__(256) gemm_bf16_kernel(
    const __nv_bfloat16* __restrict__ A, const __nv_bfloat16* __restrict__ B,
    const float* __restrict__ bias, float* __restrict__ C, int M, int N, int K)
{
    __shared__ __align__(16) __nv_bfloat16 As[2][128 * 40];
    __shared__ __align__(16) __nv_bfloat16 Bs[2][128 * 40];
    int tid = threadIdx.x, warp = tid >> 5, lane = tid & 31;
    int bm = blockIdx.y * 128, bn = blockIdx.x * 128;
    int mB = (warp >> 2) * 64, nB = (warp & 3) * 32;
    int r = lane >> 2, cc = lane & 3;

    float acc[4][4][4];
#pragma unroll
    for (int i = 0; i < 4; i++)
#pragma unroll
        for (int j = 0; j < 4; j++)
#pragma unroll
            for (int q = 0; q < 4; q++) acc[i][j][q] = 0.f;

    int rr0 = tid >> 2, c8 = (tid & 3) * 8;
    const int KT = K / 32;

    {
        cp16(smaddr(&As[0][rr0 * 40 + c8]), A + (size_t)(bm + rr0) * K + c8);
        cp16(smaddr(&Bs[0][rr0 * 40 + c8]), B + (size_t)(bn + rr0) * K + c8);
        int rr1 = rr0 + 64;
        cp16(smaddr(&As[0][rr1 * 40 + c8]), A + (size_t)(bm + rr1) * K + c8);
        cp16(smaddr(&Bs[0][rr1 * 40 + c8]), B + (size_t)(bn + rr1) * K + c8);
        cp_commit();
    }

    for (int kt = 0; kt < KT; kt++) {
        int st = kt & 1;
        if (kt + 1 < KT) {
            int k0 = (kt + 1) * 32;
            cp16(smaddr(&As[st ^ 1][rr0 * 40 + c8]), A + (size_t)(bm + rr0) * K + k0 + c8);
            cp16(smaddr(&Bs[st ^ 1][rr0 * 40 + c8]), B + (size_t)(bn + rr0) * K + k0 + c8);
            int rr1 = rr0 + 64;
            cp16(smaddr(&As[st ^ 1][rr1 * 40 + c8]), A + (size_t)(bm + rr1) * K + k0 + c8);
            cp16(smaddr(&Bs[st ^ 1][rr1 * 40 + c8]), B + (size_t)(bn + rr1) * K + k0 + c8);
            cp_commit();
            cp_wait<1>();
        } else {
            cp_wait<0>();
        }
        __syncthreads();
#pragma unroll
        for (int ks = 0; ks < 2; ks++) {
            int k = ks * 16;
            uint32_t af[4][4], bf[4][2];
#pragma unroll
            for (int mt = 0; mt < 4; mt++) {
                const __nv_bfloat16* ap = &As[st][(mB + mt * 16 + r) * 40 + k + cc * 2];
                af[mt][0] = *(const uint32_t*)(ap);
                af[mt][1] = *(const uint32_t*)(ap + 8 * 40);
                af[mt][2] = *(const uint32_t*)(ap + 8);
                af[mt][3] = *(const uint32_t*)(ap + 8 * 40 + 8);
            }
#pragma unroll
            for (int nt = 0; nt < 4; nt++) {
                const __nv_bfloat16* bp = &Bs[st][(nB + nt * 8 + r) * 40 + k + cc * 2];
                bf[nt][0] = *(const uint32_t*)(bp);
                bf[nt][1] = *(const uint32_t*)(bp + 8);
            }
#pragma unroll
            for (int mt = 0; mt < 4; mt++)
#pragma unroll
                for (int nt = 0; nt < 4; nt++)
                    mma_bf16(acc[mt][nt], af[mt], bf[nt]);
        }
        __syncthreads();
    }
#pragma unroll
    for (int mt = 0; mt < 4; mt++)
#pragma unroll
        for (int nt = 0; nt < 4; nt++) {
            int row = bm + mB + mt * 16 + r;
            int col = bn + nB + nt * 8 + cc * 2;
            float b0 = bias[col], b1 = bias[col + 1];
            float2 v0 = make_float2(acc[mt][nt][0] + b0, acc[mt][nt][1] + b1);
            float2 v1 = make_float2(acc[mt][nt][2] + b0, acc[mt][nt][3] + b1);
            *(float2*)(C + (size_t)row * N + col)       = v0;
            *(float2*)(C + (size_t)(row + 8) * N + col) = v1;
        }
}

// ---------------- persistent RNN layer: R6 smem staging + flag barrier + split stage ----------------
__global__ void __launch_bounds__(256) rnn_layer_kernel(
    const float* __restrict__ xW, const float* __restrict__ Wh,
    const float* __restrict__ h0,
    float* __restrict__ yf, __nv_bfloat16* __restrict__ yb,
    float* __restrict__ hfin, int writeBf)
{
    extern __shared__ float dyn[];
    float* Whs = dyn;                            // [16][WH_STRIDE] tf32
    float* hs  = Whs + RNN_COLS * WH_STRIDE;     // [32][WH_STRIDE] raw f32
    float* red = hs + 32 * WH_STRIDE;            // [8][512]

    int tid = threadIdx.x, warp = tid >> 5, lane = tid & 31;
    int r = lane >> 2, cc = lane & 3;
    int colBase = blockIdx.x * RNN_COLS;
    int kw = warp * 128;

    // uniform-at-launch base of the flag counters (only this CTA writes its own flag)
    unsigned base = *(volatile unsigned*)&g_flags[blockIdx.x * 32];

    // weight slice, tf32-rounded, once
    for (int i4 = tid; i4 < RNN_COLS * 256; i4 += 256) {
        int n = i4 >> 8, c4 = (i4 & 255) * 4;
        float4 v = *(const float4*)(Wh + (size_t)(colBase + n) * HID + c4);
        *(float4*)&Whs[n * WH_STRIDE + c4] =
            make_float4(f2tf(v.x), f2tf(v.y), f2tf(v.z), f2tf(v.w));
    }
    __syncthreads();

    int ob = tid >> 3;
    int on = (tid * 2) & 15;
    const float* xwp = xW + (size_t)ob * HID + colBase + on;
    float2 xwv = *(const float2*)xwp;

    for (int t = 0; t < T_SEQ; t++) {
        const float* hprev = (t == 0) ? h0 : ((t & 1) ? g_hbuf0 : g_hbuf1);
        float* hnext = (t & 1) ? g_hbuf1 : g_hbuf0;

        // per-warp stage of h K-slice, split 16+16 rows into two commit groups
        const float* hsrc = hprev + kw + lane * 4;
        float* hdst = hs + kw + lane * 4;
#pragma unroll
        for (int b = 0; b < 16; b++)
            cp16(smaddr(hdst + (size_t)b * WH_STRIDE), hsrc + (size_t)b * HID);
        cp_commit();
#pragma unroll
        for (int b = 16; b < 32; b++)
            cp16(smaddr(hdst + (size_t)b * WH_STRIDE), hsrc + (size_t)b * HID);
        cp_commit();

        float acc[2][2][4];
#pragma unroll
        for (int mt = 0; mt < 2; mt++)
#pragma unroll
            for (int nt = 0; nt < 2; nt++)
#pragma unroll
                for (int q = 0; q < 4; q++) acc[mt][nt][q] = 0.f;

        // first half ready -> mt=0 MMAs (overlaps second-half staging)
        cp_wait<1>();
        __syncwarp();
#pragma unroll
        for (int kt = 0; kt < 16; kt++) {
            int k0 = kw + kt * 8;
            uint32_t af[4], bf[2][2];
            const float* ap = &hs[r * WH_STRIDE + k0 + cc];
            af[0] = t32(ap[0]);
            af[1] = t32(ap[8 * WH_STRIDE]);
            af[2] = t32(ap[4]);
            af[3] = t32(ap[8 * WH_STRIDE + 4]);
#pragma unroll
            for (int nt = 0; nt < 2; nt++) {
                const float* bp = &Whs[(nt * 8 + r) * WH_STRIDE + k0 + cc];
                bf[nt][0] = fbits(bp[0]);
                bf[nt][1] = fbits(bp[4]);
            }
#pragma unroll
            for (int nt = 0; nt < 2; nt++)
                mma_tf32(acc[0][nt], af, bf[nt]);
        }

        // second half -> mt=1 MMAs
        cp_wait<0>();
        __syncwarp();
#pragma unroll
        for (int kt = 0; kt < 16; kt++) {
            int k0 = kw + kt * 8;
            uint32_t af[4], bf[2][2];
            const float* ap = &hs[(16 + r) * WH_STRIDE + k0 + cc];
            af[0] = t32(ap[0]);
            af[1] = t32(ap[8 * WH_STRIDE]);
            af[2] = t32(ap[4]);
            af[3] = t32(ap[8 * WH_STRIDE + 4]);
#pragma unroll
            for (int nt = 0; nt < 2; nt++) {
                const float* bp = &Whs[(nt * 8 + r) * WH_STRIDE + k0 + cc];
                bf[nt][0] = fbits(bp[0]);
                bf[nt][1] = fbits(bp[4]);
            }
#pragma unroll
            for (int nt = 0; nt < 2; nt++)
                mma_tf32(acc[1][nt], af, bf[nt]);
        }

#pragma unroll
        for (int mt = 0; mt < 2; mt++)
#pragma unroll
            for (int nt = 0; nt < 2; nt++) {
                int b = mt * 16 + r, n = nt * 8 + 2 * cc;
                *(float2*)&red[warp * 512 + b * 16 + n] =
                    make_float2(acc[mt][nt][0], acc[mt][nt][1]);
                *(float2*)&red[warp * 512 + (b + 8) * 16 + n] =
                    make_float2(acc[mt][nt][2], acc[mt][nt][3]);
            }
        __syncthreads();

        int o = tid * 2;
        float sx = 0.f, sy = 0.f;
#pragma unroll
        for (int w = 0; w < 8; w++) {
            float2 v = *(float2*)&red[w * 512 + o];
            sx += v.x; sy += v.y;
        }
        float v0 = tanhf(sx + xwv.x);
        float v1 = tanhf(sy + xwv.y);
        __stcg((float2*)(hnext + ob * HID + colBase + on), make_float2(v0, v1));
        __syncthreads();   // all h stores done before the release below

        // arrive: publish this CTA's step (release orders the h stores)
        if (t + 1 < T_SEQ && tid == 0)
            asm volatile("st.release.gpu.u32 [%0], %1;"
                         :: "l"(&g_flags[blockIdx.x * 32]), "r"(base + t + 1) : "memory");

        // overlapped with flag propagation: outputs + next xW prefetch
        if (t + 1 < T_SEQ)
            xwv = *(const float2*)(xwp + (size_t)(t + 1) * BATCH * HID);
        size_t oofs = (size_t)(t * BATCH + ob) * HID + colBase + on;
        *(float2*)(yf + oofs) = make_float2(v0, v1);
        if (writeBf) {
            __nv_bfloat162 pb;
            pb.x = __float2bfloat16_rn(v0);
            pb.y = __float2bfloat16_rn(v1);
            *(__nv_bfloat162*)(yb + oofs) = pb;
        }
        if (t == T_SEQ - 1)
            *(float2*)(hfin + ob * HID + colBase + on) = make_float2(v0, v1);

        // wait: threads 0..63 each watch one CTA's flag
        if (t + 1 < T_SEQ) {
            if (tid < RNN_CTAS) {
                unsigned tgt = base + t + 1, g;
                do {
                    asm volatile("ld.acquire.gpu.u32 %0, [%1];"
                                 : "=r"(g) : "l"(&g_flags[tid * 32]) : "memory");
                } while ((int)(g - tgt) < 0);
            }
            __syncthreads();
        }
    }
}

// ---------------- log_softmax over rows of 32000 ----------------
__device__ __forceinline__ void comb(float& m, float& s, float m2, float s2) {
    float nm = fmaxf(m, m2);
    s = s * __expf(m - nm) + s2 * __expf(m2 - nm);
    m = nm;
}
__global__ void __launch_bounds__(256) logsoftmax_kernel(float* __restrict__ out) {
    __shared__ float sm[8], ss[8], bm, bs;
    float* row = out + (size_t)blockIdx.x * VOCAB;
    int tid = threadIdx.x;
    float m = -1e30f, s = 0.f;
    for (int i = tid; i < VOCAB / 4; i += 256) {
        float4 v = *(const float4*)(row + i * 4);
        comb(m, s, v.x, 1.f); comb(m, s, v.y, 1.f);
        comb(m, s, v.z, 1.f); comb(m, s, v.w, 1.f);
    }
#pragma unroll
    for (int o = 16; o > 0; o >>= 1) {
        float m2 = __shfl_xor_sync(0xffffffffu, m, o);
        float s2 = __shfl_xor_sync(0xffffffffu, s, o);
        comb(m, s, m2, s2);
    }
    if ((tid & 31) == 0) { sm[tid >> 5] = m; ss[tid >> 5] = s; }
    __syncthreads();
    if (tid == 0) {
        float M = sm[0], S = ss[0];
#pragma unroll
        for (int w = 1; w < 8; w++) comb(M, S, sm[w], ss[w]);
        bm = M; bs = logf(S);
    }
    __syncthreads();
    float sub = bm + bs;
    for (int i = tid; i < VOCAB / 4; i += 256) {
        float4 v = *(const float4*)(row + i * 4);
        v.x -= sub; v.y -= sub; v.z -= sub; v.w -= sub;
        *(float4*)(row + i * 4) = v;
    }
}

// ---------------- append final hidden states ----------------
__global__ void __launch_bounds__(256) copy_hidden_kernel(float* __restrict__ dst) {
    int i = blockIdx.x * 256 + threadIdx.x;
    dst[i] = g_hfin[i];
}

// ---------------- launch ----------------
extern "C" void kernel_launch(void* const* d_in, const int* in_sizes, int n_in,
                              void* d_out, int out_size) {
    const int*   tok    = (const int*)d_in[0];
    const float* hidden = (const float*)d_in[1];
    const float* emb    = (const float*)d_in[2];
    const float* W_ih   = (const float*)d_in[3];
    const float* W_hh   = (const float*)d_in[4];
    const float* b_ih   = (const float*)d_in[5];
    const float* b_hh   = (const float*)d_in[6];
    const float* W_out  = (const float*)d_in[7];
    const float* b_out  = (const float*)d_in[8];
    float* out = (float*)d_out;

    void *p_x0, *p_xw, *p_y0, *p_y1b, *p_hfin, *p_wb;
    cudaGetSymbolAddress(&p_x0, g_x0);
    cudaGetSymbolAddress(&p_xw, g_xw);
    cudaGetSymbolAddress(&p_y0, g_y0);
    cudaGetSymbolAddress(&p_y1b, g_y1b);
    cudaGetSymbolAddress(&p_hfin, g_hfin);
    cudaGetSymbolAddress(&p_wb, g_woutb);

    const int rnn_smem = (RNN_COLS + 32) * WH_STRIDE * 4 + 8 * 512 * 4;
    cudaFuncSetAttribute(rnn_layer_kernel,
                         cudaFuncAttributeMaxDynamicSharedMemorySize, rnn_smem);

    embed_kernel<<<MROWS, 256>>>(tok, emb);
    cvt_wout_kernel<<<VOCAB, 256>>>(W_out);

    // layer 0
    gemm_tf32_kernel<<<dim3(HID / 128, MROWS / 128), 256>>>(
        (const float*)p_x0, W_ih, b_ih, b_hh, (float*)p_xw, MROWS, HID, HID);
    rnn_layer_kernel<<<RNN_CTAS, 256, rnn_smem>>>(
        (const float*)p_xw, W_hh, hidden,
        (float*)p_y0, (__nv_bfloat16*)p_y1b, (float*)p_hfin, 0);

    // layer 1
    gemm_tf32_kernel<<<dim3(HID / 128, MROWS / 128), 256>>>(
        (const float*)p_y0, W_ih + (size_t)HID * HID, b_ih + HID, b_hh + HID,
        (float*)p_xw, MROWS, HID, HID);
    rnn_layer_kernel<<<RNN_CTAS, 256, rnn_smem>>>(
        (const float*)p_xw, W_hh + (size_t)HID * HID, hidden + BATCH * HID,
        (float*)p_y0, (__nv_bfloat16*)p_y1b, (float*)p_hfin + BATCH * HID, 1);

    // output projection + log_softmax
    gemm_bf16_kernel<<<dim3(VOCAB / 128, MROWS / 128), 256>>>(
        (const __nv_bfloat16*)p_y1b, (const __nv_bfloat16*)p_wb, b_out, out,
        MROWS, VOCAB, HID);
    logsoftmax_kernel<<<MROWS, 256>>>(out);

    size_t logits_elems = (size_t)MROWS * VOCAB;
    if ((size_t)out_size >= logits_elems + 2 * BATCH * HID)
        copy_hidden_kernel<<<(2 * BATCH * HID) / 256, 256>>>(out + logits_elems);
}

// round 14
// speedup vs baseline: 2.0055x; 1.0939x over previous
#include <cuda_runtime.h>
#include <cuda_bf16.h>
#include <cstdint>
#include <math.h>

#define T_SEQ  128
#define BATCH  32
#define HID    1024
#define VOCAB  32000
#define MROWS  (T_SEQ * BATCH)      // 4096
#define RNN_CTAS 64
#define RNN_COLS 16                 // HID / RNN_CTAS
#define WH_STRIDE 1028              // 1024 + 4 pad (floats)

// ---------------- scratch (device globals; allocation is forbidden) ----------------
__device__ float          g_x0[MROWS * HID];
__device__ float          g_xw[MROWS * HID];
__device__ float          g_y0[MROWS * HID];
__device__ __nv_bfloat16  g_y1b[MROWS * HID];
__device__ __nv_bfloat16  g_woutb[(size_t)VOCAB * HID];
__device__ float          g_hbuf0[BATCH * HID];
__device__ float          g_hbuf1[BATCH * HID];
__device__ float          g_hfin[2 * BATCH * HID];
// one flag per CTA, 128B apart (monotonic step counters; uniform at launch edges)
__device__ __align__(128) unsigned g_flags[RNN_CTAS * 32];

// ---------------- helpers ----------------
__device__ __forceinline__ uint32_t smaddr(const void* p) {
    return (uint32_t)__cvta_generic_to_shared(p);
}
__device__ __forceinline__ void cp16(uint32_t dst, const void* src) {
    asm volatile("cp.async.ca.shared.global [%0], [%1], 16;" :: "r"(dst), "l"(src));
}
__device__ __forceinline__ void cp_commit() { asm volatile("cp.async.commit_group;"); }
template <int N> __device__ __forceinline__ void cp_wait() {
    asm volatile("cp.async.wait_group %0;" :: "n"(N));
}
__device__ __forceinline__ float f2tf(float x) {
    uint32_t r; asm("cvt.rna.tf32.f32 %0, %1;" : "=r"(r) : "f"(x));
    return __uint_as_float(r);
}
__device__ __forceinline__ uint32_t t32(float x) {
    uint32_t r; asm("cvt.rna.tf32.f32 %0, %1;" : "=r"(r) : "f"(x));
    return r;
}
__device__ __forceinline__ uint32_t fbits(float x) { return __float_as_uint(x); }

__device__ __forceinline__ void mma_tf32(float* c, const uint32_t* a, const uint32_t* b) {
    asm volatile(
        "mma.sync.aligned.m16n8k8.row.col.f32.tf32.tf32.f32 "
        "{%0,%1,%2,%3}, {%4,%5,%6,%7}, {%8,%9}, {%0,%1,%2,%3};"
        : "+f"(c[0]), "+f"(c[1]), "+f"(c[2]), "+f"(c[3])
        : "r"(a[0]), "r"(a[1]), "r"(a[2]), "r"(a[3]), "r"(b[0]), "r"(b[1]));
}
__device__ __forceinline__ void mma_bf16(float* c, const uint32_t* a, const uint32_t* b) {
    asm volatile(
        "mma.sync.aligned.m16n8k16.row.col.f32.bf16.bf16.f32 "
        "{%0,%1,%2,%3}, {%4,%5,%6,%7}, {%8,%9}, {%0,%1,%2,%3};"
        : "+f"(c[0]), "+f"(c[1]), "+f"(c[2]), "+f"(c[3])
        : "r"(a[0]), "r"(a[1]), "r"(a[2]), "r"(a[3]), "r"(b[0]), "r"(b[1]));
}

// ---------------- embedding gather ----------------
__global__ void __launch_bounds__(256) embed_kernel(const int* __restrict__ tok,
                                                    const float* __restrict__ emb) {
    int row = blockIdx.x;
    int t = tok[row];
    const float4* s = (const float4*)(emb + (size_t)t * HID);
    float4* d = (float4*)(g_x0 + (size_t)row * HID);
    d[threadIdx.x] = s[threadIdx.x];
}

// ---------------- W_out f32 -> bf16 ----------------
__global__ void __launch_bounds__(256) cvt_wout_kernel(const float* __restrict__ w) {
    size_t i = ((size_t)blockIdx.x * 256 + threadIdx.x) * 4;
    float4 v = *(const float4*)(w + i);
    __nv_bfloat162 p0, p1;
    p0.x = __float2bfloat16_rn(v.x); p0.y = __float2bfloat16_rn(v.y);
    p1.x = __float2bfloat16_rn(v.z); p1.y = __float2bfloat16_rn(v.w);
    *(__nv_bfloat162*)(g_woutb + i)     = p0;
    *(__nv_bfloat162*)(g_woutb + i + 2) = p1;
}

// ---------------- tf32 GEMM: C[M,N] = A[M,K] @ B[N,K]^T + biasA[n] + biasB[n] ----------------
__global__ void __launch_bounds__(256) gemm_tf32_kernel(
    const float* __restrict__ A, const float* __restrict__ B,
    const float* __restrict__ biasA, const float* __restrict__ biasB,
    float* __restrict__ C, int M, int N, int K)
{
    __shared__ __align__(16) float As[128 * 20];
    __shared__ __align__(16) float Bs[128 * 20];
    int tid = threadIdx.x, warp = tid >> 5, lane = tid & 31;
    int bm = blockIdx.y * 128, bn = blockIdx.x * 128;
    int mB = (warp >> 2) * 64, nB = (warp & 3) * 32;
    int r = lane >> 2, cc = lane & 3;

    float acc[4][4][4];
#pragma unroll
    for (int i = 0; i < 4; i++)
#pragma unroll
        for (int j = 0; j < 4; j++)
#pragma unroll
            for (int q = 0; q < 4; q++) acc[i][j][q] = 0.f;

    for (int k0 = 0; k0 < K; k0 += 16) {
        __syncthreads();
#pragma unroll
        for (int i = 0; i < 2; i++) {
            int q = i * 256 + tid;
            int rr = q >> 2, c4 = (q & 3) * 4;
            float4 va = *(const float4*)(A + (size_t)(bm + rr) * K + k0 + c4);
            float4 ta = make_float4(f2tf(va.x), f2tf(va.y), f2tf(va.z), f2tf(va.w));
            *(float4*)&As[rr * 20 + c4] = ta;
            float4 vb = *(const float4*)(B + (size_t)(bn + rr) * K + k0 + c4);
            float4 tb = make_float4(f2tf(vb.x), f2tf(vb.y), f2tf(vb.z), f2tf(vb.w));
            *(float4*)&Bs[rr * 20 + c4] = tb;
        }
        __syncthreads();
#pragma unroll
        for (int ks = 0; ks < 2; ks++) {
            int k = ks * 8;
            uint32_t af[4][4], bf[4][2];
#pragma unroll
            for (int mt = 0; mt < 4; mt++) {
                const float* ap = &As[(mB + mt * 16 + r) * 20 + k + cc];
                af[mt][0] = fbits(ap[0]);
                af[mt][1] = fbits(ap[8 * 20]);
                af[mt][2] = fbits(ap[4]);
                af[mt][3] = fbits(ap[8 * 20 + 4]);
            }
#pragma unroll
            for (int nt = 0; nt < 4; nt++) {
                const float* bp = &Bs[(nB + nt * 8 + r) * 20 + k + cc];
                bf[nt][0] = fbits(bp[0]);
                bf[nt][1] = fbits(bp[4]);
            }
#pragma unroll
            for (int mt = 0; mt < 4; mt++)
#pragma unroll
                for (int nt = 0; nt < 4; nt++)
                    mma_tf32(acc[mt][nt], af[mt], bf[nt]);
        }
    }
#pragma unroll
    for (int mt = 0; mt < 4; mt++)
#pragma unroll
        for (int nt = 0; nt < 4; nt++) {
            int row = bm + mB + mt * 16 + r;
            int col = bn + nB + nt * 8 + cc * 2;
            float b0 = biasA[col] + biasB[col];
            float b1 = biasA[col + 1] + biasB[col + 1];
            float2 v0 = make_float2(acc[mt][nt][0] + b0, acc[mt][nt][1] + b1);
            float2 v1 = make_float2(acc[mt][nt][2] + b0, acc[mt][nt][3] + b1);
            *(float2*)(C + (size_t)row * N + col)       = v0;
            *(float2*)(C + (size_t)(row + 8) * N + col) = v1;
        }
}

// ---------------- bf16 GEMM: C[M,N] = A[M,K] @ B[N,K]^T + bias[n] ----------------
__global__ void __launch_bounds__(256) gemm_bf16_kernel(
    const __nv_bfloat16* __restrict__ A, const __nv_bfloat16* __restrict__ B,
    const float* __restrict__ bias, float* __restrict__ C, int M, int N, int K)
{
    __shared__ __align__(16) __nv_bfloat16 As[2][128 * 40];
    __shared__ __align__(16) __nv_bfloat16 Bs[2][128 * 40];
    int tid = threadIdx.x, warp = tid >> 5, lane = tid & 31;
    int bm = blockIdx.y * 128, bn = blockIdx.x * 128;
    int mB = (warp >> 2) * 64, nB = (warp & 3) * 32;
    int r = lane >> 2, cc = lane & 3;

    float acc[4][4][4];
#pragma unroll
    for (int i = 0; i < 4; i++)
#pragma unroll
        for (int j = 0; j < 4; j++)
#pragma unroll
            for (int q = 0; q < 4; q++) acc[i][j][q] = 0.f;

    int rr0 = tid >> 2, c8 = (tid & 3) * 8;
    const int KT = K / 32;

    {
        cp16(smaddr(&As[0][rr0 * 40 + c8]), A + (size_t)(bm + rr0) * K + c8);
        cp16(smaddr(&Bs[0][rr0 * 40 + c8]), B + (size_t)(bn + rr0) * K + c8);
        int rr1 = rr0 + 64;
        cp16(smaddr(&As[0][rr1 * 40 + c8]), A + (size_t)(bm + rr1) * K + c8);
        cp16(smaddr(&Bs[0][rr1 * 40 + c8]), B + (size_t)(bn + rr1) * K + c8);
        cp_commit();
    }

    for (int kt = 0; kt < KT; kt++) {
        int st = kt & 1;
        if (kt + 1 < KT) {
            int k0 = (kt + 1) * 32;
            cp16(smaddr(&As[st ^ 1][rr0 * 40 + c8]), A + (size_t)(bm + rr0) * K + k0 + c8);
            cp16(smaddr(&Bs[st ^ 1][rr0 * 40 + c8]), B + (size_t)(bn + rr0) * K + k0 + c8);
            int rr1 = rr0 + 64;
            cp16(smaddr(&As[st ^ 1][rr1 * 40 + c8]), A + (size_t)(bm + rr1) * K + k0 + c8);
            cp16(smaddr(&Bs[st ^ 1][rr1 * 40 + c8]), B + (size_t)(bn + rr1) * K + k0 + c8);
            cp_commit();
            cp_wait<1>();
        } else {
            cp_wait<0>();
        }
        __syncthreads();
#pragma unroll
        for (int ks = 0; ks < 2; ks++) {
            int k = ks * 16;
            uint32_t af[4][4], bf[4][2];
#pragma unroll
            for (int mt = 0; mt < 4; mt++) {
                const __nv_bfloat16* ap = &As[st][(mB + mt * 16 + r) * 40 + k + cc * 2];
                af[mt][0] = *(const uint32_t*)(ap);
                af[mt][1] = *(const uint32_t*)(ap + 8 * 40);
                af[mt][2] = *(const uint32_t*)(ap + 8);
                af[mt][3] = *(const uint32_t*)(ap + 8 * 40 + 8);
            }
#pragma unroll
            for (int nt = 0; nt < 4; nt++) {
                const __nv_bfloat16* bp = &Bs[st][(nB + nt * 8 + r) * 40 + k + cc * 2];
                bf[nt][0] = *(const uint32_t*)(bp);
                bf[nt][1] = *(const uint32_t*)(bp + 8);
            }
#pragma unroll
            for (int mt = 0; mt < 4; mt++)
#pragma unroll
                for (int nt = 0; nt < 4; nt++)
                    mma_bf16(acc[mt][nt], af[mt], bf[nt]);
        }
        __syncthreads();
    }
#pragma unroll
    for (int mt = 0; mt < 4; mt++)
#pragma unroll
        for (int nt = 0; nt < 4; nt++) {
            int row = bm + mB + mt * 16 + r;
            int col = bn + nB + nt * 8 + cc * 2;
            float b0 = bias[col], b1 = bias[col + 1];
            float2 v0 = make_float2(acc[mt][nt][0] + b0, acc[mt][nt][1] + b1);
            float2 v1 = make_float2(acc[mt][nt][2] + b0, acc[mt][nt][3] + b1);
            *(float2*)(C + (size_t)row * N + col)       = v0;
            *(float2*)(C + (size_t)(row + 8) * N + col) = v1;
        }
}

// ---------------- persistent RNN layer ----------------
// R13 staging + flag barrier, plus: B-fragments hoisted to registers (loop-invariant),
// and per-warp producer-distributed flag waits (warp w waits only on CTAs 8w..8w+7).
__global__ void __launch_bounds__(256) rnn_layer_kernel(
    const float* __restrict__ xW, const float* __restrict__ Wh,
    const float* __restrict__ h0,
    float* __restrict__ yf, __nv_bfloat16* __restrict__ yb,
    float* __restrict__ hfin, int writeBf)
{
    extern __shared__ float dyn[];
    float* Whs = dyn;                            // [16][WH_STRIDE] tf32
    float* hs  = Whs + RNN_COLS * WH_STRIDE;     // [32][WH_STRIDE] raw f32
    float* red = hs + 32 * WH_STRIDE;            // [8][512]

    int tid = threadIdx.x, warp = tid >> 5, lane = tid & 31;
    int r = lane >> 2, cc = lane & 3;
    int colBase = blockIdx.x * RNN_COLS;
    int kw = warp * 128;

    // uniform-at-launch base of the flag counters (only this CTA writes its own flag)
    unsigned base = *(volatile unsigned*)&g_flags[blockIdx.x * 32];

    // weight slice, tf32-rounded, once
    for (int i4 = tid; i4 < RNN_COLS * 256; i4 += 256) {
        int n = i4 >> 8, c4 = (i4 & 255) * 4;
        float4 v = *(const float4*)(Wh + (size_t)(colBase + n) * HID + c4);
        *(float4*)&Whs[n * WH_STRIDE + c4] =
            make_float4(f2tf(v.x), f2tf(v.y), f2tf(v.z), f2tf(v.w));
    }
    __syncthreads();

    // hoist B fragments into registers: invariant over all 128 steps and both m-halves
    uint32_t Bf[16][2][2];
#pragma unroll
    for (int kt = 0; kt < 16; kt++) {
        int k0 = kw + kt * 8;
#pragma unroll
        for (int nt = 0; nt < 2; nt++) {
            const float* bp = &Whs[(nt * 8 + r) * WH_STRIDE + k0 + cc];
            Bf[kt][nt][0] = fbits(bp[0]);
            Bf[kt][nt][1] = fbits(bp[4]);
        }
    }

    int ob = tid >> 3;
    int on = (tid * 2) & 15;
    const float* xwp = xW + (size_t)ob * HID + colBase + on;
    float2 xwv = *(const float2*)xwp;

    // this warp's producer flag (lanes 0..7): CTAs 8*warp .. 8*warp+7
    const unsigned* myflag = &g_flags[(8 * warp + (lane & 7)) * 32];

    for (int t = 0; t < T_SEQ; t++) {
        const float* hprev = (t == 0) ? h0 : ((t & 1) ? g_hbuf0 : g_hbuf1);
        float* hnext = (t & 1) ? g_hbuf1 : g_hbuf0;

        // per-warp wait: only this warp's 8 producer CTAs must have published step t
        if (t > 0) {
            if (lane < 8) {
                unsigned tgt = base + t, g;
                do {
                    asm volatile("ld.acquire.gpu.u32 %0, [%1];"
                                 : "=r"(g) : "l"(myflag) : "memory");
                } while ((int)(g - tgt) < 0);
            }
            __syncwarp();
        }

        // per-warp stage of h K-slice, split 16+16 rows into two commit groups
        const float* hsrc = hprev + kw + lane * 4;
        float* hdst = hs + kw + lane * 4;
#pragma unroll
        for (int b = 0; b < 16; b++)
            cp16(smaddr(hdst + (size_t)b * WH_STRIDE), hsrc + (size_t)b * HID);
        cp_commit();
#pragma unroll
        for (int b = 16; b < 32; b++)
            cp16(smaddr(hdst + (size_t)b * WH_STRIDE), hsrc + (size_t)b * HID);
        cp_commit();

        float acc[2][2][4];
#pragma unroll
        for (int mt = 0; mt < 2; mt++)
#pragma unroll
            for (int nt = 0; nt < 2; nt++)
#pragma unroll
                for (int q = 0; q < 4; q++) acc[mt][nt][q] = 0.f;

        // first half ready -> mt=0 MMAs (overlaps second-half staging)
        cp_wait<1>();
        __syncwarp();
#pragma unroll
        for (int kt = 0; kt < 16; kt++) {
            int k0 = kw + kt * 8;
            uint32_t af[4];
            const float* ap = &hs[r * WH_STRIDE + k0 + cc];
            af[0] = t32(ap[0]);
            af[1] = t32(ap[8 * WH_STRIDE]);
            af[2] = t32(ap[4]);
            af[3] = t32(ap[8 * WH_STRIDE + 4]);
#pragma unroll
            for (int nt = 0; nt < 2; nt++)
                mma_tf32(acc[0][nt], af, Bf[kt][nt]);
        }

        // second half -> mt=1 MMAs
        cp_wait<0>();
        __syncwarp();
#pragma unroll
        for (int kt = 0; kt < 16; kt++) {
            int k0 = kw + kt * 8;
            uint32_t af[4];
            const float* ap = &hs[(16 + r) * WH_STRIDE + k0 + cc];
            af[0] = t32(ap[0]);
            af[1] = t32(ap[8 * WH_STRIDE]);
            af[2] = t32(ap[4]);
            af[3] = t32(ap[8 * WH_STRIDE + 4]);
#pragma unroll
            for (int nt = 0; nt < 2; nt++)
                mma_tf32(acc[1][nt], af, Bf[kt][nt]);
        }

#pragma unroll
        for (int mt = 0; mt < 2; mt++)
#pragma unroll
            for (int nt = 0; nt < 2; nt++) {
                int b = mt * 16 + r, n = nt * 8 + 2 * cc;
                *(float2*)&red[warp * 512 + b * 16 + n] =
                    make_float2(acc[mt][nt][0], acc[mt][nt][1]);
                *(float2*)&red[warp * 512 + (b + 8) * 16 + n] =
                    make_float2(acc[mt][nt][2], acc[mt][nt][3]);
            }
        __syncthreads();

        int o = tid * 2;
        float sx = 0.f, sy = 0.f;
#pragma unroll
        for (int w = 0; w < 8; w++) {
            float2 v = *(float2*)&red[w * 512 + o];
            sx += v.x; sy += v.y;
        }
        float v0 = tanhf(sx + xwv.x);
        float v1 = tanhf(sy + xwv.y);
        __stcg((float2*)(hnext + ob * HID + colBase + on), make_float2(v0, v1));
        __syncthreads();   // all CTA h-stores + red reads done before release / reuse

        // arrive: publish this CTA's step (release orders the h stores)
        if (t + 1 < T_SEQ && tid == 0)
            asm volatile("st.release.gpu.u32 [%0], %1;"
                         :: "l"(&g_flags[blockIdx.x * 32]), "r"(base + t + 1) : "memory");

        // overlapped with flag propagation: outputs + next xW prefetch
        if (t + 1 < T_SEQ)
            xwv = *(const float2*)(xwp + (size_t)(t + 1) * BATCH * HID);
        size_t oofs = (size_t)(t * BATCH + ob) * HID + colBase + on;
        *(float2*)(yf + oofs) = make_float2(v0, v1);
        if (writeBf) {
            __nv_bfloat162 pb;
            pb.x = __float2bfloat16_rn(v0);
            pb.y = __float2bfloat16_rn(v1);
            *(__nv_bfloat162*)(yb + oofs) = pb;
        }
        if (t == T_SEQ - 1)
            *(float2*)(hfin + ob * HID + colBase + on) = make_float2(v0, v1);
    }
}

// ---------------- log_softmax over rows of 32000 ----------------
__device__ __forceinline__ void comb(float& m, float& s, float m2, float s2) {
    float nm = fmaxf(m, m2);
    s = s * __expf(m - nm) + s2 * __expf(m2 - nm);
    m = nm;
}
__global__ void __launch_bounds__(256) logsoftmax_kernel(float* __restrict__ out) {
    __shared__ float sm[8], ss[8], bm, bs;
    float* row = out + (size_t)blockIdx.x * VOCAB;
    int tid = threadIdx.x;
    float m = -1e30f, s = 0.f;
    for (int i = tid; i < VOCAB / 4; i += 256) {
        float4 v = *(const float4*)(row + i * 4);
        comb(m, s, v.x, 1.f); comb(m, s, v.y, 1.f);
        comb(m, s, v.z, 1.f); comb(m, s, v.w, 1.f);
    }
#pragma unroll
    for (int o = 16; o > 0; o >>= 1) {
        float m2 = __shfl_xor_sync(0xffffffffu, m, o);
        float s2 = __shfl_xor_sync(0xffffffffu, s, o);
        comb(m, s, m2, s2);
    }
    if ((tid & 31) == 0) { sm[tid >> 5] = m; ss[tid >> 5] = s; }
    __syncthreads();
    if (tid == 0) {
        float M = sm[0], S = ss[0];
#pragma unroll
        for (int w = 1; w < 8; w++) comb(M, S, sm[w], ss[w]);
        bm = M; bs = logf(S);
    }
    __syncthreads();
    float sub = bm + bs;
    for (int i = tid; i < VOCAB / 4; i += 256) {
        float4 v = *(const float4*)(row + i * 4);
        v.x -= sub; v.y -= sub; v.z -= sub; v.w -= sub;
        *(float4*)(row + i * 4) = v;
    }
}

// ---------------- append final hidden states ----------------
__global__ void __launch_bounds__(256) copy_hidden_kernel(float* __restrict__ dst) {
    int i = blockIdx.x * 256 + threadIdx.x;
    dst[i] = g_hfin[i];
}

// ---------------- launch ----------------
extern "C" void kernel_launch(void* const* d_in, const int* in_sizes, int n_in,
                              void* d_out, int out_size) {
    const int*   tok    = (const int*)d_in[0];
    const float* hidden = (const float*)d_in[1];
    const float* emb    = (const float*)d_in[2];
    const float* W_ih   = (const float*)d_in[3];
    const float* W_hh   = (const float*)d_in[4];
    const float* b_ih   = (const float*)d_in[5];
    const float* b_hh   = (const float*)d_in[6];
    const float* W_out  = (const float*)d_in[7];
    const float* b_out  = (const float*)d_in[8];
    float* out = (float*)d_out;

    void *p_x0, *p_xw, *p_y0, *p_y1b, *p_hfin, *p_wb;
    cudaGetSymbolAddress(&p_x0, g_x0);
    cudaGetSymbolAddress(&p_xw, g_xw);
    cudaGetSymbolAddress(&p_y0, g_y0);
    cudaGetSymbolAddress(&p_y1b, g_y1b);
    cudaGetSymbolAddress(&p_hfin, g_hfin);
    cudaGetSymbolAddress(&p_wb, g_woutb);

    const int rnn_smem = (RNN_COLS + 32) * WH_STRIDE * 4 + 8 * 512 * 4;
    cudaFuncSetAttribute(rnn_layer_kernel,
                         cudaFuncAttributeMaxDynamicSharedMemorySize, rnn_smem);

    embed_kernel<<<MROWS, 256>>>(tok, emb);
    cvt_wout_kernel<<<VOCAB, 256>>>(W_out);

    // layer 0
    gemm_tf32_kernel<<<dim3(HID / 128, MROWS / 128), 256>>>(
        (const float*)p_x0, W_ih, b_ih, b_hh, (float*)p_xw, MROWS, HID, HID);
    rnn_layer_kernel<<<RNN_CTAS, 256, rnn_smem>>>(
        (const float*)p_xw, W_hh, hidden,
        (float*)p_y0, (__nv_bfloat16*)p_y1b, (float*)p_hfin, 0);

    // layer 1
    gemm_tf32_kernel<<<dim3(HID / 128, MROWS / 128), 256>>>(
        (const float*)p_y0, W_ih + (size_t)HID * HID, b_ih + HID, b_hh + HID,
        (float*)p_xw, MROWS, HID, HID);
    rnn_layer_kernel<<<RNN_CTAS, 256, rnn_smem>>>(
        (const float*)p_xw, W_hh + (size_t)HID * HID, hidden + BATCH * HID,
        (float*)p_y0, (__nv_bfloat16*)p_y1b, (float*)p_hfin + BATCH * HID, 1);

    // output projection + log_softmax
    gemm_bf16_kernel<<<dim3(VOCAB / 128, MROWS / 128), 256>>>(
        (const __nv_bfloat16*)p_y1b, (const __nv_bfloat16*)p_wb, b_out, out,
        MROWS, VOCAB, HID);
    logsoftmax_kernel<<<MROWS, 256>>>(out);

    size_t logits_elems = (size_t)MROWS * VOCAB;
    if ((size_t)out_size >= logits_elems + 2 * BATCH * HID)
        copy_hidden_kernel<<<(2 * BATCH * HID) / 256, 256>>>(out + logits_elems);
}